// round 11
// baseline (speedup 1.0000x reference)
#include <cuda_runtime.h>

// Problem dims (fixed by the dataset)
#define Bn 8
#define Cn 19
#define Hn 384
#define Wn 384
#define NPIX (Bn * Hn * Wn)
#define HWn (Hn * Wn)
#define BOUND 777  // B + C + H + W = 8+1+384+384
#define CE_BLOCKS ((NPIX / 4) / 256)   // 1152

// Accumulators (zero-init at load; last block resets them each run)
__device__ float        g_ce;
__device__ unsigned int g_border;
__device__ unsigned int g_cnt;

// ---------------------------------------------------------------------------
// target-border value at (r,c), recomputed from targets (pad semantics):
// tb(r,c) = ((t(r+1,c)-t(r,c)) + (t(r,c+1)-t(r,c))) != 0, diffs 0 at edges.
// ---------------------------------------------------------------------------
__device__ __forceinline__ int tb_at(const int* __restrict__ t, int r, int c) {
    int t0 = __ldg(t + r * Wn + c);
    int tD = (r < Hn - 1) ? __ldg(t + (r + 1) * Wn + c) : t0;
    int tR = (c < Wn - 1) ? __ldg(t + r * Wn + c + 1) : t0;
    return ((tD - t0) + (tR - t0)) != 0;
}

// argmax over channels at one pixel (first-max tie break, same order as main)
__device__ __forceinline__ int argmax_at(const float* __restrict__ px) {
    float m = __ldg(px);
    int a = 0;
    #pragma unroll
    for (int c = 1; c < Cn; c++) {
        float v = __ldg(px + (size_t)c * HWn);
        if (v > m) { m = v; a = c; }
    }
    return a;
}

// Exact expanding-ring Chebyshev search from radius 2, borders recomputed
// from targets (no dependency on other blocks). Essentially never executed.
__device__ __noinline__ int ring_search(const int* __restrict__ t, int gi, int gj) {
    for (int tt = 2; tt <= Hn + Wn; tt++) {
        int found = 0;
        int ra = gi - tt, rb = gi + tt;
        int ca = gj - tt, cb = gj + tt;
        int cl = ca > 0 ? ca : 0;
        int cr = cb < Wn - 1 ? cb : Wn - 1;
        if (ra >= 0) for (int c = cl; c <= cr; c++) found |= tb_at(t, ra, c);
        if (rb < Hn) for (int c = cl; c <= cr; c++) found |= tb_at(t, rb, c);
        int rl = (ra + 1) > 0 ? (ra + 1) : 0;
        int rh = (rb - 1) < Hn - 1 ? (rb - 1) : Hn - 1;
        if (ca >= 0) for (int r = rl; r <= rh; r++) found |= tb_at(t, r, ca);
        if (cb < Wn) for (int r = rl; r <= rh; r++) found |= tb_at(t, r, cb);
        if (found) return tt;
        if (ra < 0 && rb >= Hn && ca < 0 && cb >= Wn) break;  // no border anywhere
    }
    return BOUND;
}

// ---------------------------------------------------------------------------
// SINGLE fused kernel: CE(sum, ignore=255) + argmax + target borders + border
// loss, all in one pass. 4 pixels/thread via float4/int4. Rare pixels
// (tb==0, ~2.6%) resolve their distance locally: ring-1 borders recomputed
// from targets (L2-hot), missing pred values re-argmaxed from slices
// (L2-resident: 89.6MB fits in 126MB L2). Last block finalizes + resets.
// ---------------------------------------------------------------------------
__global__ void __launch_bounds__(256, 2) fused_kernel(
    const float* __restrict__ x, const int* __restrict__ tgt,
    float* __restrict__ out) {
    int idx4 = blockIdx.x * blockDim.x + threadIdx.x;  // 0 .. NPIX/4-1
    const int HW4 = HWn / 4;
    int b = idx4 / HW4;
    int hw4 = idx4 - b * HW4;
    const float* xb = x + (size_t)b * Cn * HWn;        // batch base
    const float4* p = (const float4*)xb + hw4;
    const int* tb_img = tgt + b * HWn;

    float v[Cn][4];
    #pragma unroll
    for (int c = 0; c < Cn; c++) {
        float4 q = __ldg(p + (size_t)c * HW4);
        v[c][0] = q.x; v[c][1] = q.y; v[c][2] = q.z; v[c][3] = q.w;
    }

    int hw = hw4 * 4;
    int i = hw / Wn;                 // row (4 pixels always within one row)
    int j0 = hw - i * Wn;            // col of pixel 0

    int4 tq = __ldg((const int4*)tgt + idx4);
    int t[5];
    t[0] = tq.x; t[1] = tq.y; t[2] = tq.z; t[3] = tq.w;
    t[4] = (j0 + 4 < Wn) ? __ldg(tb_img + i * Wn + j0 + 4) : t[3];  // row-end pad

    int td[4];
    if (i < Hn - 1) {
        int4 dq = __ldg((const int4*)tgt + idx4 + Wn / 4);
        td[0] = dq.x; td[1] = dq.y; td[2] = dq.z; td[3] = dq.w;
    } else {
        td[0] = t[0]; td[1] = t[1]; td[2] = t[2]; td[3] = t[3];  // bottom pad
    }

    float nll = 0.0f;
    int arg[4];
    int tbb[4];
    #pragma unroll
    for (int k = 0; k < 4; k++) {
        float m = v[0][k];
        int a = 0;
        float tv = v[0][k];
        #pragma unroll
        for (int c = 1; c < Cn; c++) {
            float vc = v[c][k];
            if (vc > m) { m = vc; a = c; }       // first-max tie break
            tv = (c == t[k]) ? vc : tv;           // register-resident gather
        }
        arg[k] = a;
        tbb[k] = (((td[k] - t[k]) + (t[k + 1] - t[k])) != 0);

        float s = 0.0f;
        #pragma unroll
        for (int c = 0; c < Cn; c++) s += __expf(v[c][k] - m);

        if (t[k] != 255) nll += (m + __logf(s)) - tv;
    }

    // ---- border loss for rare pixels (tb==0): resolved locally ----
    int contrib = 0;
    #pragma unroll
    for (int k = 0; k < 4; k++) {
        if (tbb[k]) continue;                    // tb==1 -> d=0 -> adds 0
        int gj = j0 + k;

        // pred border: p0 local; right/down pred re-argmaxed when not local.
        int p0 = arg[k];
        int pr;
        if (k < 3)            pr = arg[k + 1];
        else if (gj < Wn - 1) pr = argmax_at(xb + i * Wn + gj + 1);
        else                  pr = p0;
        int pd = (i < Hn - 1) ? argmax_at(xb + (i + 1) * Wn + gj) : p0;
        if (((pd - p0) + (pr - p0)) == 0) continue;

        // ring-1 target borders recomputed from targets (L2-hot)
        int f = 0;
        #pragma unroll
        for (int dr = -1; dr <= 1; dr++) {
            #pragma unroll
            for (int dc = -1; dc <= 1; dc++) {
                if (dr == 0 && dc == 0) continue;
                int r = i + dr, c = gj + dc;
                if (r >= 0 && r < Hn && c >= 0 && c < Wn)
                    f |= tb_at(tb_img, r, c);
            }
        }
        contrib += f ? 1 : ring_search(tb_img, i, gj);
    }

    // ---- block reductions (float nll + int contrib) -> atomics ----
    #pragma unroll
    for (int o = 16; o > 0; o >>= 1) {
        nll     += __shfl_down_sync(0xFFFFFFFFu, nll, o);
        contrib += __shfl_down_sync(0xFFFFFFFFu, contrib, o);
    }
    __shared__ float ws[8];
    __shared__ int   wsum[8];
    int lane = threadIdx.x & 31, wid = threadIdx.x >> 5;
    if (lane == 0) { ws[wid] = nll; wsum[wid] = contrib; }
    __syncthreads();
    if (wid == 0) {
        float f2 = (lane < 8) ? ws[lane] : 0.0f;
        int   i2 = (lane < 8) ? wsum[lane] : 0;
        #pragma unroll
        for (int o = 4; o > 0; o >>= 1) {
            f2 += __shfl_down_sync(0xFFFFFFFFu, f2, o);
            i2 += __shfl_down_sync(0xFFFFFFFFu, i2, o);
        }
        if (lane == 0) {
            atomicAdd(&g_ce, f2);
            if (i2) atomicAdd(&g_border, (unsigned int)i2);
            __threadfence();
            unsigned int done = atomicAdd(&g_cnt, 1u);
            if (done == CE_BLOCKS - 1) {        // last block: finalize + reset
                __threadfence();
                out[0] = g_ce + 0.2f * (float)g_border;
                g_ce = 0.0f;
                g_border = 0u;
                g_cnt = 0u;
            }
        }
    }
}

extern "C" void kernel_launch(void* const* d_in, const int* in_sizes, int n_in,
                              void* d_out, int out_size) {
    const float* slices  = (const float*)d_in[0];
    const int*   targets = (const int*)d_in[1];   // JAX int64 -> int32 (x64 disabled)
    float* out = (float*)d_out;

    fused_kernel<<<CE_BLOCKS, 256>>>(slices, targets, out);
}

// round 12
// speedup vs baseline: 1.7815x; 1.7815x over previous
#include <cuda_runtime.h>

// Problem dims (fixed by the dataset)
#define Bn 8
#define Cn 19
#define Hn 384
#define Wn 384
#define NPIX (Bn * Hn * Wn)
#define HWn (Hn * Wn)
#define BOUND 777  // B + C + H + W = 8+1+384+384
#define DT_GRID 148
#define DT_THREADS 256

// Scratch (allocation-free rule: __device__ globals), 16B-aligned for uint4 IO
__device__ __align__(16) unsigned char g_pred[NPIX];
__device__ __align__(16) unsigned char g_tb[NPIX];    // target-border bitmap (0/1)
__device__ __align__(16) int g_rare[NPIX];  // pixels with tb==0 (~2.6% = 31k)
__device__ float        g_ce;          // zero-init at load; last dt block resets
__device__ unsigned int g_border;      // ditto
__device__ unsigned int g_cnt;         // ditto
__device__ unsigned int g_nrare;       // ditto

// ---------------------------------------------------------------------------
// Kernel 1: fused CE(sum, ignore=255) + argmax(pred map) + target-border map
// + WARP-AGGREGATED compaction of candidate pixels (tb==0) into g_rare.
// 4 pixels/thread via float4/int4; 19 channel float4s in registers (max pass,
// then independent exp sum -> no serial MUFU chain). Register-lean: rides HBM.
// border(i,j) = ((t[i+1,j]-t[i,j]) + (t[i,j+1]-t[i,j])) != 0, zero-padded.
// ---------------------------------------------------------------------------
__global__ void __launch_bounds__(256) ce_kernel(
    const float* __restrict__ x, const int* __restrict__ tgt) {
    int idx4 = blockIdx.x * blockDim.x + threadIdx.x;  // 0 .. NPIX/4-1
    const int HW4 = HWn / 4;
    int b = idx4 / HW4;
    int hw4 = idx4 - b * HW4;
    const float4* p = (const float4*)(x + (size_t)b * Cn * HWn) + hw4;

    float v[Cn][4];
    #pragma unroll
    for (int c = 0; c < Cn; c++) {
        float4 q = __ldg(p + (size_t)c * HW4);
        v[c][0] = q.x; v[c][1] = q.y; v[c][2] = q.z; v[c][3] = q.w;
    }

    int hw = hw4 * 4;
    int i = hw / Wn;                 // row (4 pixels always within one row)
    int j0 = hw - i * Wn;            // col of pixel 0
    int gbase = b * HWn + hw;        // global pixel index of pixel 0

    int4 tq = __ldg((const int4*)tgt + idx4);
    int t[5];
    t[0] = tq.x; t[1] = tq.y; t[2] = tq.z; t[3] = tq.w;
    t[4] = (j0 + 4 < Wn) ? __ldg(tgt + gbase + 4) : t[3];   // row-end pad

    int td[4];
    if (i < Hn - 1) {
        int4 dq = __ldg((const int4*)tgt + idx4 + Wn / 4);
        td[0] = dq.x; td[1] = dq.y; td[2] = dq.z; td[3] = dq.w;
    } else {
        td[0] = t[0]; td[1] = t[1]; td[2] = t[2]; td[3] = t[3];  // bottom pad
    }

    float nll = 0.0f;
    unsigned int packed_pred = 0, packed_border = 0;
    #pragma unroll
    for (int k = 0; k < 4; k++) {
        float m = v[0][k];
        int arg = 0;
        float tv = v[0][k];
        #pragma unroll
        for (int c = 1; c < Cn; c++) {
            float vc = v[c][k];
            if (vc > m) { m = vc; arg = c; }     // first-max tie break
            tv = (c == t[k]) ? vc : tv;           // register-resident gather
        }
        packed_pred |= ((unsigned int)arg) << (8 * k);

        int bd = (((td[k] - t[k]) + (t[k + 1] - t[k])) != 0) ? 1 : 0;
        packed_border |= ((unsigned int)bd) << (8 * k);

        float s = 0.0f;
        #pragma unroll
        for (int c = 0; c < Cn; c++) s += __expf(v[c][k] - m);

        if (t[k] != 255) nll += (m + __logf(s)) - tv;
    }
    ((unsigned int*)g_pred)[idx4] = packed_pred;
    ((unsigned int*)g_tb)[idx4]   = packed_border;

    int lane = threadIdx.x & 31, wid = threadIdx.x >> 5;

    // Warp-aggregated compaction of candidate pixels (tb byte == 0).
    {
        int nr = 0;
        #pragma unroll
        for (int k = 0; k < 4; k++)
            nr += (((packed_border >> (8 * k)) & 0xFFu) == 0u);

        // inclusive warp scan of nr
        int scan = nr;
        #pragma unroll
        for (int o = 1; o < 32; o <<= 1) {
            int sv = __shfl_up_sync(0xFFFFFFFFu, scan, o);
            if (lane >= o) scan += sv;
        }
        int total = __shfl_sync(0xFFFFFFFFu, scan, 31);
        if (total > 0) {
            unsigned int base = 0;
            if (lane == 31) base = atomicAdd(&g_nrare, (unsigned int)total);
            base = __shfl_sync(0xFFFFFFFFu, base, 31);
            int off = (int)base + scan - nr;
            #pragma unroll
            for (int k = 0; k < 4; k++) {
                if (((packed_border >> (8 * k)) & 0xFFu) == 0u)
                    g_rare[off++] = gbase + k;
            }
        }
    }

    // block reduction -> atomicAdd
    #pragma unroll
    for (int o = 16; o > 0; o >>= 1)
        nll += __shfl_down_sync(0xFFFFFFFFu, nll, o);
    __shared__ float ws[8];
    if (lane == 0) ws[wid] = nll;
    __syncthreads();
    if (wid == 0) {
        float v2 = (lane < (blockDim.x >> 5)) ? ws[lane] : 0.0f;
        #pragma unroll
        for (int o = 4; o > 0; o >>= 1)
            v2 += __shfl_down_sync(0xFFFFFFFFu, v2, o);
        if (lane == 0) atomicAdd(&g_ce, v2);
    }
}

// ---------------------------------------------------------------------------
// Kernel 2: border loss over the compacted candidate list, 4 PIXELS/THREAD.
// One coalesced int4 read of the rare list, then all 4 pixels' scattered
// loads (3 pred + 8 ring-1 border bytes each, clamped + masked, branch-free)
// issued as one independent batch -> 2 L2 round trips total, 4x MLP.
// Exact expanding-ring fallback from tt=2 (essentially never taken).
// LAST BLOCK finalizes out = g_ce + 0.2*border and resets accumulators.
// ---------------------------------------------------------------------------
__global__ void __launch_bounds__(DT_THREADS) dt_kernel(float* __restrict__ out) {
    __shared__ int wsum[DT_THREADS / 32];

    int n = (int)g_nrare;
    int nq = (n + 3) >> 2;
    int contrib = 0;
    for (int q = blockIdx.x * blockDim.x + threadIdx.x; q < nq;
         q += gridDim.x * blockDim.x) {
        int4 px4 = __ldg((const int4*)g_rare + q);
        int pixv[4] = {px4.x, px4.y, px4.z, px4.w};
        int qbase = q * 4;

        int pix[4], gi[4], gj[4], hwv[4], bb[4];
        int p0[4], pr[4], pd[4], f[4], valid[4];
        #pragma unroll
        for (int e = 0; e < 4; e++) {
            valid[e] = (qbase + e < n);
            pix[e] = valid[e] ? pixv[e] : 0;     // clamp -> safe addresses
            bb[e] = pix[e] / HWn;
            hwv[e] = pix[e] - bb[e] * HWn;
            gi[e] = hwv[e] / Wn;
            gj[e] = hwv[e] - gi[e] * Wn;
        }
        // --- batched independent loads for all 4 pixels (one round trip) ---
        #pragma unroll
        for (int e = 0; e < 4; e++) {
            const unsigned char* tb = g_tb + bb[e] * HWn;
            int hasU = (gi[e] > 0), hasD = (gi[e] < Hn - 1);
            int hasL = (gj[e] > 0), hasR = (gj[e] < Wn - 1);
            p0[e] = g_pred[pix[e]];
            pr[e] = g_pred[pix[e] + hasR];
            pd[e] = g_pred[pix[e] + hasD * Wn];
            int cu = hwv[e] - hasU * Wn, cd = hwv[e] + hasD * Wn;
            int ff = 0;
            ff |= (int)tb[cu - hasL] & (hasU & hasL);
            ff |= (int)tb[cu]        &  hasU;
            ff |= (int)tb[cu + hasR] & (hasU & hasR);
            ff |= (int)tb[hwv[e] - hasL] & hasL;
            ff |= (int)tb[hwv[e] + hasR] & hasR;
            ff |= (int)tb[cd - hasL] & (hasD & hasL);
            ff |= (int)tb[cd]        &  hasD;
            ff |= (int)tb[cd + hasR] & (hasD & hasR);
            f[e] = ff;
        }
        // --- evaluate ---
        #pragma unroll
        for (int e = 0; e < 4; e++) {
            bool pb = (((pd[e] - p0[e]) + (pr[e] - p0[e])) != 0);
            if (!valid[e] || !pb) continue;
            if (f[e]) {
                contrib += 1;
            } else {
                // exact expanding-ring Chebyshev fallback (~never taken)
                const unsigned char* tb = g_tb + bb[e] * HWn;
                int d = BOUND;
                for (int tt = 2; tt <= Hn + Wn; tt++) {
                    bool g = false;
                    int ra = gi[e] - tt, rb = gi[e] + tt;
                    int ca = gj[e] - tt, cb = gj[e] + tt;
                    int cl = ca > 0 ? ca : 0;
                    int cr = cb < Wn - 1 ? cb : Wn - 1;
                    if (ra >= 0) for (int c = cl; c <= cr; c++) g |= tb[ra * Wn + c] != 0;
                    if (rb < Hn) for (int c = cl; c <= cr; c++) g |= tb[rb * Wn + c] != 0;
                    int rl = (ra + 1) > 0 ? (ra + 1) : 0;
                    int rh = (rb - 1) < Hn - 1 ? (rb - 1) : Hn - 1;
                    if (ca >= 0) for (int r = rl; r <= rh; r++) g |= tb[r * Wn + ca] != 0;
                    if (cb < Wn) for (int r = rl; r <= rh; r++) g |= tb[r * Wn + cb] != 0;
                    if (g) { d = tt; break; }
                    if (ra < 0 && rb >= Hn && ca < 0 && cb >= Wn) break;
                }
                contrib += d;
            }
        }
    }

    // integer block reduction (exact) -> u32 atomic
    #pragma unroll
    for (int o = 16; o > 0; o >>= 1)
        contrib += __shfl_down_sync(0xFFFFFFFFu, contrib, o);
    int lane = threadIdx.x & 31, wid = threadIdx.x >> 5;
    if (lane == 0) wsum[wid] = contrib;
    __syncthreads();
    if (wid == 0) {
        int v2 = (lane < (DT_THREADS / 32)) ? wsum[lane] : 0;
        #pragma unroll
        for (int o = 4; o > 0; o >>= 1)
            v2 += __shfl_down_sync(0xFFFFFFFFu, v2, o);
        if (lane == 0) {
            atomicAdd(&g_border, (unsigned int)v2);
            __threadfence();
            unsigned int done = atomicAdd(&g_cnt, 1u);
            if (done == gridDim.x - 1) {       // last block: finalize + reset
                __threadfence();
                out[0] = g_ce + 0.2f * (float)g_border;
                g_ce = 0.0f;
                g_border = 0u;
                g_cnt = 0u;
                g_nrare = 0u;
            }
        }
    }
}

extern "C" void kernel_launch(void* const* d_in, const int* in_sizes, int n_in,
                              void* d_out, int out_size) {
    const float* slices  = (const float*)d_in[0];
    const int*   targets = (const int*)d_in[1];   // JAX int64 -> int32 (x64 disabled)
    float* out = (float*)d_out;

    ce_kernel<<<(NPIX / 4) / 256, 256>>>(slices, targets);
    dt_kernel<<<DT_GRID, DT_THREADS>>>(out);
}